// round 1
// baseline (speedup 1.0000x reference)
#include <cuda_runtime.h>
#include <cuda_bf16.h>
#include <math.h>

#define N 4096
#define D 1024
#define NUM_NEG 100

// ---------------- scratch (device globals; no allocation allowed) ----------
__device__ float g_A[N * D];     // projection A / z1 combined
__device__ float g_B[N * D];     // projection B / z2 combined
__device__ float g_H[N * D];     // hidden temp
__device__ float g_rowsum[N];
__device__ float g_colsum[N];
__device__ float g_mrow[N];
__device__ float g_mcol[N];
__device__ float g_lse[N];
__device__ double g_s[4];        // [0]=gcl1 logsum, [1]=gcl2 logsum, [2]=pair_sum, [3]=pair_cnt

// ---------------- small utility kernels ------------------------------------
__global__ void zero_scalars_k(double* s) {
    if (threadIdx.x < 4) s[threadIdx.x] = 0.0;
}

__global__ void zero_rowcol_k(float* a, float* b) {
    int i = blockIdx.x * blockDim.x + threadIdx.x;
    if (i < N) { a[i] = 0.f; b[i] = 0.f; }
}

// z1 = (1-g)*zmp1 + g*zsc1 ; z2 = (1-g)*zmp2 + g*zsc2
__global__ void combine_k(const float* __restrict__ zmp1, const float* __restrict__ zsc1,
                          const float* __restrict__ zmp2, const float* __restrict__ zsc2,
                          const float* __restrict__ gamma,
                          float* __restrict__ z1, float* __restrict__ z2) {
    float g = *gamma;
    int i = blockIdx.x * blockDim.x + threadIdx.x;
    int idx = i * 4;
    if (idx < N * D) {
        float4 a1 = *(const float4*)&zmp1[idx];
        float4 b1 = *(const float4*)&zsc1[idx];
        float4 a2 = *(const float4*)&zmp2[idx];
        float4 b2 = *(const float4*)&zsc2[idx];
        float4 o1, o2;
        o1.x = (1.f-g)*a1.x + g*b1.x; o1.y = (1.f-g)*a1.y + g*b1.y;
        o1.z = (1.f-g)*a1.z + g*b1.z; o1.w = (1.f-g)*a1.w + g*b1.w;
        o2.x = (1.f-g)*a2.x + g*b2.x; o2.y = (1.f-g)*a2.y + g*b2.y;
        o2.z = (1.f-g)*a2.z + g*b2.z; o2.w = (1.f-g)*a2.w + g*b2.w;
        *(float4*)&z1[idx] = o1;
        *(float4*)&z2[idx] = o2;
    }
}

// normalize rows in place (one warp per row)
__global__ void normalize_k(float* __restrict__ P) {
    int warp = (blockIdx.x * blockDim.x + threadIdx.x) >> 5;
    int lane = threadIdx.x & 31;
    if (warp >= N) return;
    float* row = P + (size_t)warp * D;
    float ss = 0.f;
    #pragma unroll 8
    for (int d = lane; d < D; d += 32) { float v = row[d]; ss += v * v; }
    #pragma unroll
    for (int o = 16; o; o >>= 1) ss += __shfl_xor_sync(0xffffffffu, ss, o);
    float inv = 1.0f / sqrtf(ss);
    #pragma unroll 8
    for (int d = lane; d < D; d += 32) row[d] *= inv;
}

// ---------------- tiled NT GEMM: C[i,j] = sum_k A[i,k]*B[j,k] (+bias, opt ELU)
#define BM 128
#define BN 128
#define BK 16

template <int ELU>
__global__ __launch_bounds__(256)
void gemm_nt_bias_k(const float* __restrict__ A, const float* __restrict__ B,
                    const float* __restrict__ bias, float* __restrict__ C,
                    int K, int Nc) {
    __shared__ float As[BK][BM];
    __shared__ float Bs[BK][BN];
    int tid = threadIdx.x;
    int tx = tid & 15, ty = tid >> 4;
    int m0 = blockIdx.y * BM, n0 = blockIdx.x * BN;
    float acc[8][8] = {};
    for (int kt = 0; kt < K; kt += BK) {
        #pragma unroll
        for (int l = 0; l < 2; l++) {
            int idx = tid + l * 256;
            int row = idx >> 2, kc = (idx & 3) << 2;
            float4 va = *(const float4*)&A[(size_t)(m0 + row) * K + kt + kc];
            As[kc][row] = va.x; As[kc+1][row] = va.y; As[kc+2][row] = va.z; As[kc+3][row] = va.w;
            float4 vb = *(const float4*)&B[(size_t)(n0 + row) * K + kt + kc];
            Bs[kc][row] = vb.x; Bs[kc+1][row] = vb.y; Bs[kc+2][row] = vb.z; Bs[kc+3][row] = vb.w;
        }
        __syncthreads();
        #pragma unroll
        for (int k = 0; k < BK; k++) {
            float a[8], b[8];
            #pragma unroll
            for (int i = 0; i < 4; i++) {
                a[i]     = As[k][ty * 4 + i];
                a[i + 4] = As[k][ty * 4 + i + 64];
                b[i]     = Bs[k][tx * 4 + i];
                b[i + 4] = Bs[k][tx * 4 + i + 64];
            }
            #pragma unroll
            for (int y = 0; y < 8; y++)
                #pragma unroll
                for (int x = 0; x < 8; x++)
                    acc[y][x] = fmaf(a[y], b[x], acc[y][x]);
        }
        __syncthreads();
    }
    #pragma unroll
    for (int iy = 0; iy < 8; iy++) {
        int r = m0 + ((iy < 4) ? (ty * 4 + iy) : (ty * 4 + iy - 4 + 64));
        #pragma unroll
        for (int ix = 0; ix < 8; ix++) {
            int c = n0 + ((ix < 4) ? (tx * 4 + ix) : (tx * 4 + ix - 4 + 64));
            float v = acc[iy][ix] + bias[c];
            if (ELU) v = (v > 0.f) ? v : expm1f(v);
            C[(size_t)r * Nc + c] = v;
        }
    }
}

// ---------------- sim GEMM: e=exp(cos/0.8), fused row/col sums, no C write --
__global__ __launch_bounds__(256)
void sim_gemm_k(const float* __restrict__ A, const float* __restrict__ B,
                float* __restrict__ rowsum, float* __restrict__ colsum) {
    __shared__ float As[BK][BM];
    __shared__ float Bs[BK][BN];
    __shared__ float srow[BM];
    __shared__ float scol[BN];
    int tid = threadIdx.x;
    int tx = tid & 15, ty = tid >> 4;
    int m0 = blockIdx.y * BM, n0 = blockIdx.x * BN;
    float acc[8][8] = {};
    for (int kt = 0; kt < D; kt += BK) {
        #pragma unroll
        for (int l = 0; l < 2; l++) {
            int idx = tid + l * 256;
            int row = idx >> 2, kc = (idx & 3) << 2;
            float4 va = *(const float4*)&A[(size_t)(m0 + row) * D + kt + kc];
            As[kc][row] = va.x; As[kc+1][row] = va.y; As[kc+2][row] = va.z; As[kc+3][row] = va.w;
            float4 vb = *(const float4*)&B[(size_t)(n0 + row) * D + kt + kc];
            Bs[kc][row] = vb.x; Bs[kc+1][row] = vb.y; Bs[kc+2][row] = vb.z; Bs[kc+3][row] = vb.w;
        }
        __syncthreads();
        #pragma unroll
        for (int k = 0; k < BK; k++) {
            float a[8], b[8];
            #pragma unroll
            for (int i = 0; i < 4; i++) {
                a[i]     = As[k][ty * 4 + i];
                a[i + 4] = As[k][ty * 4 + i + 64];
                b[i]     = Bs[k][tx * 4 + i];
                b[i + 4] = Bs[k][tx * 4 + i + 64];
            }
            #pragma unroll
            for (int y = 0; y < 8; y++)
                #pragma unroll
                for (int x = 0; x < 8; x++)
                    acc[y][x] = fmaf(a[y], b[x], acc[y][x]);
        }
        __syncthreads();
    }
    if (tid < BM) { srow[tid] = 0.f; scol[tid] = 0.f; }
    __syncthreads();
    float rpart[8] = {}, cpart[8] = {};
    #pragma unroll
    for (int iy = 0; iy < 8; iy++)
        #pragma unroll
        for (int ix = 0; ix < 8; ix++) {
            float e = expf(acc[iy][ix] * 1.25f);   // 1/TAU = 1/0.8
            rpart[iy] += e;
            cpart[ix] += e;
        }
    #pragma unroll
    for (int iy = 0; iy < 8; iy++) {
        int r = (iy < 4) ? (ty * 4 + iy) : (ty * 4 + iy - 4 + 64);
        atomicAdd(&srow[r], rpart[iy]);
    }
    #pragma unroll
    for (int ix = 0; ix < 8; ix++) {
        int c = (ix < 4) ? (tx * 4 + ix) : (tx * 4 + ix - 4 + 64);
        atomicAdd(&scol[c], cpart[ix]);
    }
    __syncthreads();
    if (tid < BM) {
        atomicAdd(&rowsum[m0 + tid], srow[tid]);
        atomicAdd(&colsum[n0 + tid], scol[tid]);
    }
}

// ---------------- sparse masked sums for gcl (warp per row) ----------------
__global__ void gcl_pairs_k(const float* __restrict__ A, const float* __restrict__ B,
                            const float* __restrict__ pos,
                            float* __restrict__ mrow, float* __restrict__ mcol) {
    int warp = (blockIdx.x * blockDim.x + threadIdx.x) >> 5;
    int lane = threadIdx.x & 31;
    if (warp >= N) return;
    int i = warp;
    const float* pr = pos + (size_t)i * N;
    const float* Ai = A + (size_t)i * D;
    const float* Bi = B + (size_t)i * D;
    float mr = 0.f, mc = 0.f;
    for (int jb = 0; jb < N; jb += 32) {
        float pv = pr[jb + lane];
        unsigned mask = __ballot_sync(0xffffffffu, pv > 0.f);
        while (mask) {
            int b = __ffs(mask) - 1;
            mask &= mask - 1;
            int j = jb + b;
            const float* Bj = B + (size_t)j * D;
            const float* Aj = A + (size_t)j * D;
            float d1 = 0.f, d2 = 0.f;
            #pragma unroll 8
            for (int d = lane; d < D; d += 32) {
                d1 = fmaf(Ai[d], Bj[d], d1);
                d2 = fmaf(Aj[d], Bi[d], d2);
            }
            #pragma unroll
            for (int o = 16; o; o >>= 1) {
                d1 += __shfl_xor_sync(0xffffffffu, d1, o);
                d2 += __shfl_xor_sync(0xffffffffu, d2, o);
            }
            mr += expf(d1 * 1.25f);
            mc += expf(d2 * 1.25f);
        }
    }
    if (lane == 0) { mrow[i] = mr; mcol[i] = mc; }
}

// ---------------- lori reduction: sum_i [log(mrow)-log(rs+eps)+log(mcol)-log(cs+eps)]
__global__ void lori_reduce_k(const float* __restrict__ mrow, const float* __restrict__ rowsum,
                              const float* __restrict__ mcol, const float* __restrict__ colsum,
                              double* __restrict__ target) {
    __shared__ float sm[8];
    int i = blockIdx.x * blockDim.x + threadIdx.x;
    float v = 0.f;
    if (i < N)
        v = logf(mrow[i]) - logf(rowsum[i] + 1e-8f)
          + logf(mcol[i]) - logf(colsum[i] + 1e-8f);
    #pragma unroll
    for (int o = 16; o; o >>= 1) v += __shfl_xor_sync(0xffffffffu, v, o);
    int lane = threadIdx.x & 31, w = threadIdx.x >> 5;
    if (lane == 0) sm[w] = v;
    __syncthreads();
    if (threadIdx.x < 8) {
        float t = sm[threadIdx.x];
        #pragma unroll
        for (int o = 4; o; o >>= 1) t += __shfl_xor_sync(0xffu, t, o);
        if (threadIdx.x == 0) atomicAdd(target, (double)t);
    }
}

// ---------------- InfoNCE: per-row LSE over 100 pseudo-random negatives ----
__global__ __launch_bounds__(128)
void neg_lse_k(const float* __restrict__ z1, const float* __restrict__ z2,
               const float* __restrict__ md, float* __restrict__ lse) {
    __shared__ float zrow[D];
    __shared__ int idxs[NUM_NEG];
    __shared__ float vals[NUM_NEG];
    int i = blockIdx.x;
    for (int d = threadIdx.x; d < D; d += blockDim.x)
        zrow[d] = z1[(size_t)i * D + d];
    if (threadIdx.x == 0) {
        const float* mr = md + (size_t)i * N;
        unsigned start = ((unsigned)i * 2654435761u) & (N - 1);
        int cnt = 0;
        for (unsigned t = 0; cnt < NUM_NEG; t++) {
            int c = (start + t * 97u) & (N - 1);
            if (mr[c] == 0.f) idxs[cnt++] = c;
        }
    }
    __syncthreads();
    int warp = threadIdx.x >> 5, lane = threadIdx.x & 31;
    for (int k = warp; k < NUM_NEG; k += 4) {
        const float* zc = z2 + (size_t)idxs[k] * D;
        float s = 0.f;
        #pragma unroll 8
        for (int d = lane; d < D; d += 32) s = fmaf(zrow[d], zc[d], s);
        #pragma unroll
        for (int o = 16; o; o >>= 1) s += __shfl_xor_sync(0xffffffffu, s, o);
        if (lane == 0) vals[k] = s;
    }
    __syncthreads();
    if (threadIdx.x == 0) {
        float m = -1e30f;
        for (int k = 0; k < NUM_NEG; k++) m = fmaxf(m, vals[k]);
        float ss = 0.f;
        for (int k = 0; k < NUM_NEG; k++) ss += expf((vals[k] - m) * 10.0f);
        lse[i] = m * 10.0f + logf(ss);   // 1/INFONCE_TAU = 10
    }
}

// ---------------- InfoNCE positive pairs (warp per row) --------------------
__global__ void inf_pairs_k(const float* __restrict__ z1, const float* __restrict__ z2,
                            const float* __restrict__ md, const float* __restrict__ lse,
                            double* __restrict__ s) {
    int warp = (blockIdx.x * blockDim.x + threadIdx.x) >> 5;
    int lane = threadIdx.x & 31;
    if (warp >= N) return;
    int i = warp;
    const float* mr = md + (size_t)i * N;
    const float* Zi = z1 + (size_t)i * D;
    float L = lse[i];
    float sum = 0.f;
    int cnt = 0;
    for (int jb = 0; jb < N; jb += 32) {
        float pv = mr[jb + lane];
        unsigned mask = __ballot_sync(0xffffffffu, pv > 0.f);
        while (mask) {
            int b = __ffs(mask) - 1;
            mask &= mask - 1;
            int j = jb + b;
            const float* Zj = z2 + (size_t)j * D;
            float dot = 0.f;
            #pragma unroll 8
            for (int d = lane; d < D; d += 32) dot = fmaf(Zi[d], Zj[d], dot);
            #pragma unroll
            for (int o = 16; o; o >>= 1) dot += __shfl_xor_sync(0xffffffffu, dot, o);
            float p = dot * 10.0f;
            float mx = fmaxf(p, L);
            float pp = mx + logf(expf(p - mx) + expf(L - mx)) - p;
            sum += pp;
            cnt++;
        }
    }
    if (lane == 0) {
        atomicAdd(&s[2], (double)sum);
        atomicAdd(&s[3], (double)cnt);
    }
}

// ---------------- finalize --------------------------------------------------
__global__ void finalize_k(float* out, const double* s) {
    double gcl = -0.5 * (s[0] + s[1]) / (double)N;   // LAM=0.5 both directions
    out[0] = (float)(gcl + s[2] / s[3]);
}

// ---------------- launcher --------------------------------------------------
extern "C" void kernel_launch(void* const* d_in, const int* in_sizes, int n_in,
                              void* d_out, int out_size) {
    const float* z_mp1 = (const float*)d_in[0];
    const float* z_sc1 = (const float*)d_in[1];
    const float* pos1  = (const float*)d_in[2];
    const float* z_mp2 = (const float*)d_in[3];
    const float* z_sc2 = (const float*)d_in[4];
    const float* pos2  = (const float*)d_in[5];
    const float* md    = (const float*)d_in[6];
    const float* gamma = (const float*)d_in[7];
    const float* W1 = (const float*)d_in[8];
    const float* b1 = (const float*)d_in[9];
    const float* W2 = (const float*)d_in[10];
    const float* b2 = (const float*)d_in[11];
    float* out = (float*)d_out;

    float *gA, *gB, *gH, *grow, *gcol, *gmr, *gmc, *glse;
    double* gs;
    cudaGetSymbolAddress((void**)&gA, g_A);
    cudaGetSymbolAddress((void**)&gB, g_B);
    cudaGetSymbolAddress((void**)&gH, g_H);
    cudaGetSymbolAddress((void**)&grow, g_rowsum);
    cudaGetSymbolAddress((void**)&gcol, g_colsum);
    cudaGetSymbolAddress((void**)&gmr, g_mrow);
    cudaGetSymbolAddress((void**)&gmc, g_mcol);
    cudaGetSymbolAddress((void**)&glse, g_lse);
    cudaGetSymbolAddress((void**)&gs, g_s);

    zero_scalars_k<<<1, 32>>>(gs);

    dim3 gproj(D / BN, N / BM);      // (8, 32)
    dim3 gsim(N / BN, N / BM);       // (32, 32)

    const float* zmps[2] = {z_mp1, z_mp2};
    const float* zscs[2] = {z_sc1, z_sc2};
    const float* poss[2] = {pos1, pos2};
    for (int r = 0; r < 2; r++) {
        gemm_nt_bias_k<1><<<gproj, 256>>>(zmps[r], W1, b1, gH, D, D);
        gemm_nt_bias_k<0><<<gproj, 256>>>(gH, W2, b2, gA, D, D);
        gemm_nt_bias_k<1><<<gproj, 256>>>(zscs[r], W1, b1, gH, D, D);
        gemm_nt_bias_k<0><<<gproj, 256>>>(gH, W2, b2, gB, D, D);
        normalize_k<<<N / 8, 256>>>(gA);
        normalize_k<<<N / 8, 256>>>(gB);
        zero_rowcol_k<<<N / 256, 256>>>(grow, gcol);
        sim_gemm_k<<<gsim, 256>>>(gA, gB, grow, gcol);
        gcl_pairs_k<<<N / 8, 256>>>(gA, gB, poss[r], gmr, gmc);
        lori_reduce_k<<<N / 256, 256>>>(gmr, grow, gmc, gcol, &gs[r]);
    }

    combine_k<<<(N * D / 4 + 255) / 256, 256>>>(z_mp1, z_sc1, z_mp2, z_sc2, gamma, gA, gB);
    neg_lse_k<<<N, 128>>>(gA, gB, md, glse);
    inf_pairs_k<<<N / 8, 256>>>(gA, gB, md, glse, gs);
    finalize_k<<<1, 1>>>(out, gs);
}

// round 3
// speedup vs baseline: 2.4632x; 2.4632x over previous
#include <cuda_runtime.h>
#include <cuda_bf16.h>
#include <cstdint>
#include <math.h>

#define N 4096
#define D 1024
#define NUM_NEG 100

// ---------------- scratch (device globals; no allocation allowed) ----------
__device__ float g_A[N * D];             // projection out A (fp32)
__device__ float g_B[N * D];             // projection out B (fp32)
__device__ __nv_bfloat16 g_zbf[N * D];   // bf16 input staging
__device__ __nv_bfloat16 g_Hbf[N * D];   // bf16 hidden
__device__ __nv_bfloat16 g_Abf[N * D];   // bf16 normalized A
__device__ __nv_bfloat16 g_Bbf[N * D];   // bf16 normalized B
__device__ __nv_bfloat16 g_W1bf[D * D];
__device__ __nv_bfloat16 g_W2bf[D * D];
__device__ float g_rowsum[N];
__device__ float g_colsum[N];
__device__ float g_mrow[N];
__device__ float g_mcol[N];
__device__ float g_lse[N];
__device__ double g_s[4];  // [0]=gcl1 logsum, [1]=gcl2 logsum, [2]=pair_sum, [3]=pair_cnt

// ---------------- small utility kernels ------------------------------------
__global__ void zero_scalars_k(double* s) {
    if (threadIdx.x < 4) s[threadIdx.x] = 0.0;
}

__global__ void zero_rowcol_k(float* a, float* b) {
    int i = blockIdx.x * blockDim.x + threadIdx.x;
    if (i < N) { a[i] = 0.f; b[i] = 0.f; }
}

__global__ void conv_bf16_k(const float* __restrict__ src, __nv_bfloat16* __restrict__ dst, int n) {
    int idx = (blockIdx.x * blockDim.x + threadIdx.x) * 4;
    if (idx < n) {
        float4 v = *(const float4*)&src[idx];
        __nv_bfloat162 lo = __floats2bfloat162_rn(v.x, v.y);
        __nv_bfloat162 hi = __floats2bfloat162_rn(v.z, v.w);
        *(__nv_bfloat162*)&dst[idx] = lo;
        *(__nv_bfloat162*)&dst[idx + 2] = hi;
    }
}

// z1 = (1-g)*zmp1 + g*zsc1 ; z2 = (1-g)*zmp2 + g*zsc2
__global__ void combine_k(const float* __restrict__ zmp1, const float* __restrict__ zsc1,
                          const float* __restrict__ zmp2, const float* __restrict__ zsc2,
                          const float* __restrict__ gamma,
                          float* __restrict__ z1, float* __restrict__ z2) {
    float g = *gamma;
    int i = blockIdx.x * blockDim.x + threadIdx.x;
    int idx = i * 4;
    if (idx < N * D) {
        float4 a1 = *(const float4*)&zmp1[idx];
        float4 b1 = *(const float4*)&zsc1[idx];
        float4 a2 = *(const float4*)&zmp2[idx];
        float4 b2 = *(const float4*)&zsc2[idx];
        float4 o1, o2;
        o1.x = (1.f-g)*a1.x + g*b1.x; o1.y = (1.f-g)*a1.y + g*b1.y;
        o1.z = (1.f-g)*a1.z + g*b1.z; o1.w = (1.f-g)*a1.w + g*b1.w;
        o2.x = (1.f-g)*a2.x + g*b2.x; o2.y = (1.f-g)*a2.y + g*b2.y;
        o2.z = (1.f-g)*a2.z + g*b2.z; o2.w = (1.f-g)*a2.w + g*b2.w;
        *(float4*)&z1[idx] = o1;
        *(float4*)&z2[idx] = o2;
    }
}

// normalize rows in place (fp32) and emit bf16 copy (one warp per row)
__global__ void normalize_k(float* __restrict__ P, __nv_bfloat16* __restrict__ Pbf) {
    int warp = (blockIdx.x * blockDim.x + threadIdx.x) >> 5;
    int lane = threadIdx.x & 31;
    if (warp >= N) return;
    float* row = P + (size_t)warp * D;
    __nv_bfloat16* brow = Pbf + (size_t)warp * D;
    float ss = 0.f;
    #pragma unroll 8
    for (int d = lane; d < D; d += 32) { float v = row[d]; ss += v * v; }
    #pragma unroll
    for (int o = 16; o; o >>= 1) ss += __shfl_xor_sync(0xffffffffu, ss, o);
    float inv = 1.0f / sqrtf(ss);
    #pragma unroll 8
    for (int d = lane; d < D; d += 32) {
        float v = row[d] * inv;
        row[d] = v;
        brow[d] = __float2bfloat16(v);
    }
}

// ---------------- bf16 tensor-core NT GEMM ---------------------------------
// C[i,j] = sum_k A[i,k] * B[j,k]   (A: [M,K] bf16 rm, B: [Nc,K] bf16 rm)
// MODE 0: +bias, ELU, write bf16    MODE 1: +bias, write f32
// MODE 2: sim — exp(acc*1.25) fused row/col sums, no C write
#define BKT 32
#define LDB 40   // padded smem row length (bf16 elems)

__device__ __forceinline__ uint32_t ld32s(const __nv_bfloat16* p) {
    return *(const uint32_t*)p;
}

__device__ __forceinline__ void mma16816(float* c, const uint32_t* a, const uint32_t* b) {
    asm volatile(
        "mma.sync.aligned.m16n8k16.row.col.f32.bf16.bf16.f32 "
        "{%0,%1,%2,%3}, {%4,%5,%6,%7}, {%8,%9}, {%0,%1,%2,%3};"
        : "+f"(c[0]), "+f"(c[1]), "+f"(c[2]), "+f"(c[3])
        : "r"(a[0]), "r"(a[1]), "r"(a[2]), "r"(a[3]), "r"(b[0]), "r"(b[1]));
}

__device__ __forceinline__ void tile_cp_async(
    const __nv_bfloat16* __restrict__ A, const __nv_bfloat16* __restrict__ B,
    int m0, int n0, int kt, int K,
    __nv_bfloat16* as, __nv_bfloat16* bs, int tid) {
    #pragma unroll
    for (int l = 0; l < 2; l++) {
        int idx = tid + l * 256;
        int row = idx >> 2, seg = idx & 3;
        unsigned da = (unsigned)__cvta_generic_to_shared(&as[row * LDB + seg * 8]);
        const __nv_bfloat16* ga = &A[(size_t)(m0 + row) * K + kt + seg * 8];
        asm volatile("cp.async.cg.shared.global [%0], [%1], 16;" :: "r"(da), "l"(ga));
        unsigned db = (unsigned)__cvta_generic_to_shared(&bs[row * LDB + seg * 8]);
        const __nv_bfloat16* gb = &B[(size_t)(n0 + row) * K + kt + seg * 8];
        asm volatile("cp.async.cg.shared.global [%0], [%1], 16;" :: "r"(db), "l"(gb));
    }
}

template <int MODE>
__global__ __launch_bounds__(256)
void mm_bf16_k(const __nv_bfloat16* __restrict__ A, const __nv_bfloat16* __restrict__ B,
               const float* __restrict__ bias, void* __restrict__ Cout,
               float* __restrict__ rowsum, float* __restrict__ colsum,
               int K, int Nc) {
    __shared__ __align__(16) __nv_bfloat16 As[2][128 * LDB];
    __shared__ __align__(16) __nv_bfloat16 Bs[2][128 * LDB];
    __shared__ float srow[128];
    __shared__ float scol[128];

    int tid = threadIdx.x;
    int warp = tid >> 5, lane = tid & 31;
    int g = lane >> 2, t4 = lane & 3;
    int wm = (warp >> 2) * 64;   // 2 warp-rows x 64
    int wn = (warp & 3) * 32;    // 4 warp-cols x 32
    int m0 = blockIdx.y * 128, n0 = blockIdx.x * 128;

    float acc[4][4][4] = {};

    tile_cp_async(A, B, m0, n0, 0, K, As[0], Bs[0], tid);
    asm volatile("cp.async.commit_group;");

    int nt = K / BKT;
    for (int kt = 0; kt < nt; kt++) {
        if (kt + 1 < nt) {
            tile_cp_async(A, B, m0, n0, (kt + 1) * BKT, K, As[(kt + 1) & 1], Bs[(kt + 1) & 1], tid);
            asm volatile("cp.async.commit_group;");
            asm volatile("cp.async.wait_group 1;");
        } else {
            asm volatile("cp.async.wait_group 0;");
        }
        __syncthreads();
        const __nv_bfloat16* as = As[kt & 1];
        const __nv_bfloat16* bs = Bs[kt & 1];
        #pragma unroll
        for (int ks = 0; ks < 2; ks++) {
            int k0 = ks * 16 + t4 * 2;
            uint32_t a[4][4], b[4][2];
            #pragma unroll
            for (int mi = 0; mi < 4; mi++) {
                int r = wm + mi * 16 + g;
                a[mi][0] = ld32s(&as[r * LDB + k0]);
                a[mi][1] = ld32s(&as[(r + 8) * LDB + k0]);
                a[mi][2] = ld32s(&as[r * LDB + k0 + 8]);
                a[mi][3] = ld32s(&as[(r + 8) * LDB + k0 + 8]);
            }
            #pragma unroll
            for (int ni = 0; ni < 4; ni++) {
                int c = wn + ni * 8 + g;
                b[ni][0] = ld32s(&bs[c * LDB + k0]);
                b[ni][1] = ld32s(&bs[c * LDB + k0 + 8]);
            }
            #pragma unroll
            for (int mi = 0; mi < 4; mi++)
                #pragma unroll
                for (int ni = 0; ni < 4; ni++)
                    mma16816(acc[mi][ni], a[mi], b[ni]);
        }
        __syncthreads();
    }

    if (MODE == 2) {
        if (tid < 128) { srow[tid] = 0.f; scol[tid] = 0.f; }
        __syncthreads();
        float rp[4][2] = {}, cp[4][2] = {};
        #pragma unroll
        for (int mi = 0; mi < 4; mi++)
            #pragma unroll
            for (int ni = 0; ni < 4; ni++) {
                float e0 = expf(acc[mi][ni][0] * 1.25f);
                float e1 = expf(acc[mi][ni][1] * 1.25f);
                float e2 = expf(acc[mi][ni][2] * 1.25f);
                float e3 = expf(acc[mi][ni][3] * 1.25f);
                rp[mi][0] += e0 + e1;
                rp[mi][1] += e2 + e3;
                cp[ni][0] += e0 + e2;
                cp[ni][1] += e1 + e3;
            }
        #pragma unroll
        for (int mi = 0; mi < 4; mi++) {
            atomicAdd(&srow[wm + mi * 16 + g], rp[mi][0]);
            atomicAdd(&srow[wm + mi * 16 + g + 8], rp[mi][1]);
        }
        #pragma unroll
        for (int ni = 0; ni < 4; ni++) {
            atomicAdd(&scol[wn + ni * 8 + t4 * 2], cp[ni][0]);
            atomicAdd(&scol[wn + ni * 8 + t4 * 2 + 1], cp[ni][1]);
        }
        __syncthreads();
        if (tid < 128) {
            atomicAdd(&rowsum[m0 + tid], srow[tid]);
            atomicAdd(&colsum[n0 + tid], scol[tid]);
        }
    } else {
        #pragma unroll
        for (int mi = 0; mi < 4; mi++) {
            int r0 = m0 + wm + mi * 16 + g;
            #pragma unroll
            for (int ni = 0; ni < 4; ni++) {
                int c = n0 + wn + ni * 8 + t4 * 2;
                float2 bc = *(const float2*)&bias[c];
                float v0 = acc[mi][ni][0] + bc.x;
                float v1 = acc[mi][ni][1] + bc.y;
                float v2 = acc[mi][ni][2] + bc.x;
                float v3 = acc[mi][ni][3] + bc.y;
                if (MODE == 0) {
                    v0 = (v0 > 0.f) ? v0 : expm1f(v0);
                    v1 = (v1 > 0.f) ? v1 : expm1f(v1);
                    v2 = (v2 > 0.f) ? v2 : expm1f(v2);
                    v3 = (v3 > 0.f) ? v3 : expm1f(v3);
                    __nv_bfloat16* C = (__nv_bfloat16*)Cout;
                    *(__nv_bfloat162*)&C[(size_t)r0 * Nc + c] = __floats2bfloat162_rn(v0, v1);
                    *(__nv_bfloat162*)&C[(size_t)(r0 + 8) * Nc + c] = __floats2bfloat162_rn(v2, v3);
                } else {
                    float* C = (float*)Cout;
                    *(float2*)&C[(size_t)r0 * Nc + c] = make_float2(v0, v1);
                    *(float2*)&C[(size_t)(r0 + 8) * Nc + c] = make_float2(v2, v3);
                }
            }
        }
    }
}

// ---------------- sparse masked sums for gcl (warp per row) ----------------
__global__ void gcl_pairs_k(const float* __restrict__ A, const float* __restrict__ B,
                            const float* __restrict__ pos,
                            float* __restrict__ mrow, float* __restrict__ mcol) {
    int warp = (blockIdx.x * blockDim.x + threadIdx.x) >> 5;
    int lane = threadIdx.x & 31;
    if (warp >= N) return;
    int i = warp;
    const float* pr = pos + (size_t)i * N;
    const float* Ai = A + (size_t)i * D;
    const float* Bi = B + (size_t)i * D;
    float mr = 0.f, mc = 0.f;
    for (int jb = 0; jb < N; jb += 32) {
        float pv = pr[jb + lane];
        unsigned mask = __ballot_sync(0xffffffffu, pv > 0.f);
        while (mask) {
            int b = __ffs(mask) - 1;
            mask &= mask - 1;
            int j = jb + b;
            const float* Bj = B + (size_t)j * D;
            const float* Aj = A + (size_t)j * D;
            float d1 = 0.f, d2 = 0.f;
            #pragma unroll 8
            for (int d = lane; d < D; d += 32) {
                d1 = fmaf(Ai[d], Bj[d], d1);
                d2 = fmaf(Aj[d], Bi[d], d2);
            }
            #pragma unroll
            for (int o = 16; o; o >>= 1) {
                d1 += __shfl_xor_sync(0xffffffffu, d1, o);
                d2 += __shfl_xor_sync(0xffffffffu, d2, o);
            }
            mr += expf(d1 * 1.25f);
            mc += expf(d2 * 1.25f);
        }
    }
    if (lane == 0) { mrow[i] = mr; mcol[i] = mc; }
}

// ---------------- lori reduction --------------------------------------------
__global__ void lori_reduce_k(const float* __restrict__ mrow, const float* __restrict__ rowsum,
                              const float* __restrict__ mcol, const float* __restrict__ colsum,
                              double* __restrict__ target) {
    __shared__ float sm[8];
    int i = blockIdx.x * blockDim.x + threadIdx.x;
    float v = 0.f;
    if (i < N)
        v = logf(mrow[i]) - logf(rowsum[i] + 1e-8f)
          + logf(mcol[i]) - logf(colsum[i] + 1e-8f);
    #pragma unroll
    for (int o = 16; o; o >>= 1) v += __shfl_xor_sync(0xffffffffu, v, o);
    int lane = threadIdx.x & 31, w = threadIdx.x >> 5;
    if (lane == 0) sm[w] = v;
    __syncthreads();
    if (threadIdx.x < 8) {
        float t = sm[threadIdx.x];
        #pragma unroll
        for (int o = 4; o; o >>= 1) t += __shfl_xor_sync(0xffu, t, o);
        if (threadIdx.x == 0) atomicAdd(target, (double)t);
    }
}

// ---------------- InfoNCE: per-row LSE over 100 pseudo-random negatives ----
__global__ __launch_bounds__(128)
void neg_lse_k(const float* __restrict__ z1, const float* __restrict__ z2,
               const float* __restrict__ md, float* __restrict__ lse) {
    __shared__ float zrow[D];
    __shared__ int idxs[NUM_NEG];
    __shared__ float vals[NUM_NEG];
    int i = blockIdx.x;
    for (int d = threadIdx.x; d < D; d += blockDim.x)
        zrow[d] = z1[(size_t)i * D + d];
    if (threadIdx.x == 0) {
        const float* mr = md + (size_t)i * N;
        unsigned start = ((unsigned)i * 2654435761u) & (N - 1);
        int cnt = 0;
        for (unsigned t = 0; cnt < NUM_NEG; t++) {
            int c = (start + t * 97u) & (N - 1);
            if (mr[c] == 0.f) idxs[cnt++] = c;
        }
    }
    __syncthreads();
    int warp = threadIdx.x >> 5, lane = threadIdx.x & 31;
    for (int k = warp; k < NUM_NEG; k += 4) {
        const float* zc = z2 + (size_t)idxs[k] * D;
        float s = 0.f;
        #pragma unroll 8
        for (int d = lane; d < D; d += 32) s = fmaf(zrow[d], zc[d], s);
        #pragma unroll
        for (int o = 16; o; o >>= 1) s += __shfl_xor_sync(0xffffffffu, s, o);
        if (lane == 0) vals[k] = s;
    }
    __syncthreads();
    if (threadIdx.x == 0) {
        float m = -1e30f;
        for (int k = 0; k < NUM_NEG; k++) m = fmaxf(m, vals[k]);
        float ss = 0.f;
        for (int k = 0; k < NUM_NEG; k++) ss += expf((vals[k] - m) * 10.0f);
        lse[i] = m * 10.0f + logf(ss);   // 1/INFONCE_TAU = 10
    }
}

// ---------------- InfoNCE positive pairs (warp per row) --------------------
__global__ void inf_pairs_k(const float* __restrict__ z1, const float* __restrict__ z2,
                            const float* __restrict__ md, const float* __restrict__ lse,
                            double* __restrict__ s) {
    int warp = (blockIdx.x * blockDim.x + threadIdx.x) >> 5;
    int lane = threadIdx.x & 31;
    if (warp >= N) return;
    int i = warp;
    const float* mr = md + (size_t)i * N;
    const float* Zi = z1 + (size_t)i * D;
    float L = lse[i];
    float sum = 0.f;
    int cnt = 0;
    for (int jb = 0; jb < N; jb += 32) {
        float pv = mr[jb + lane];
        unsigned mask = __ballot_sync(0xffffffffu, pv > 0.f);
        while (mask) {
            int b = __ffs(mask) - 1;
            mask &= mask - 1;
            int j = jb + b;
            const float* Zj = z2 + (size_t)j * D;
            float dot = 0.f;
            #pragma unroll 8
            for (int d = lane; d < D; d += 32) dot = fmaf(Zi[d], Zj[d], dot);
            #pragma unroll
            for (int o = 16; o; o >>= 1) dot += __shfl_xor_sync(0xffffffffu, dot, o);
            float p = dot * 10.0f;
            float mx = fmaxf(p, L);
            float pp = mx + logf(expf(p - mx) + expf(L - mx)) - p;
            sum += pp;
            cnt++;
        }
    }
    if (lane == 0) {
        atomicAdd(&s[2], (double)sum);
        atomicAdd(&s[3], (double)cnt);
    }
}

// ---------------- finalize --------------------------------------------------
__global__ void finalize_k(float* out, const double* s) {
    double gcl = -0.5 * (s[0] + s[1]) / (double)N;   // LAM=0.5 both directions
    out[0] = (float)(gcl + s[2] / s[3]);
}

// ---------------- launcher --------------------------------------------------
extern "C" void kernel_launch(void* const* d_in, const int* in_sizes, int n_in,
                              void* d_out, int out_size) {
    const float* z_mp1 = (const float*)d_in[0];
    const float* z_sc1 = (const float*)d_in[1];
    const float* pos1  = (const float*)d_in[2];
    const float* z_mp2 = (const float*)d_in[3];
    const float* z_sc2 = (const float*)d_in[4];
    const float* pos2  = (const float*)d_in[5];
    const float* md    = (const float*)d_in[6];
    const float* gamma = (const float*)d_in[7];
    const float* W1 = (const float*)d_in[8];
    const float* b1 = (const float*)d_in[9];
    const float* W2 = (const float*)d_in[10];
    const float* b2 = (const float*)d_in[11];
    float* out = (float*)d_out;

    float *gA, *gB, *grow, *gcol, *gmr, *gmc, *glse;
    __nv_bfloat16 *gzbf, *gHbf, *gAbf, *gBbf, *gW1bf, *gW2bf;
    double* gs;
    cudaGetSymbolAddress((void**)&gA, g_A);
    cudaGetSymbolAddress((void**)&gB, g_B);
    cudaGetSymbolAddress((void**)&gzbf, g_zbf);
    cudaGetSymbolAddress((void**)&gHbf, g_Hbf);
    cudaGetSymbolAddress((void**)&gAbf, g_Abf);
    cudaGetSymbolAddress((void**)&gBbf, g_Bbf);
    cudaGetSymbolAddress((void**)&gW1bf, g_W1bf);
    cudaGetSymbolAddress((void**)&gW2bf, g_W2bf);
    cudaGetSymbolAddress((void**)&grow, g_rowsum);
    cudaGetSymbolAddress((void**)&gcol, g_colsum);
    cudaGetSymbolAddress((void**)&gmr, g_mrow);
    cudaGetSymbolAddress((void**)&gmc, g_mcol);
    cudaGetSymbolAddress((void**)&glse, g_lse);
    cudaGetSymbolAddress((void**)&gs, g_s);

    zero_scalars_k<<<1, 32>>>(gs);

    // weight conversion (cheap, done per call for determinism)
    conv_bf16_k<<<(D * D / 4 + 255) / 256, 256>>>(W1, gW1bf, D * D);
    conv_bf16_k<<<(D * D / 4 + 255) / 256, 256>>>(W2, gW2bf, D * D);

    dim3 gproj(D / 128, N / 128);    // (8, 32)
    dim3 gsim(N / 128, N / 128);     // (32, 32)

    const float* zmps[2] = {z_mp1, z_mp2};
    const float* zscs[2] = {z_sc1, z_sc2};
    const float* poss[2] = {pos1, pos2};
    for (int r = 0; r < 2; r++) {
        conv_bf16_k<<<(N * D / 4 + 255) / 256, 256>>>(zmps[r], gzbf, N * D);
        mm_bf16_k<0><<<gproj, 256>>>(gzbf, gW1bf, b1, gHbf, nullptr, nullptr, D, D);
        mm_bf16_k<1><<<gproj, 256>>>(gHbf, gW2bf, b2, gA, nullptr, nullptr, D, D);
        conv_bf16_k<<<(N * D / 4 + 255) / 256, 256>>>(zscs[r], gzbf, N * D);
        mm_bf16_k<0><<<gproj, 256>>>(gzbf, gW1bf, b1, gHbf, nullptr, nullptr, D, D);
        mm_bf16_k<1><<<gproj, 256>>>(gHbf, gW2bf, b2, gB, nullptr, nullptr, D, D);
        normalize_k<<<N / 8, 256>>>(gA, gAbf);
        normalize_k<<<N / 8, 256>>>(gB, gBbf);
        zero_rowcol_k<<<N / 256, 256>>>(grow, gcol);
        mm_bf16_k<2><<<gsim, 256>>>(gAbf, gBbf, nullptr, nullptr, grow, gcol, D, N);
        gcl_pairs_k<<<N / 8, 256>>>(gA, gB, poss[r], gmr, gmc);
        lori_reduce_k<<<N / 256, 256>>>(gmr, grow, gmc, gcol, &gs[r]);
    }

    combine_k<<<(N * D / 4 + 255) / 256, 256>>>(z_mp1, z_sc1, z_mp2, z_sc2, gamma, gA, gB);
    neg_lse_k<<<N, 128>>>(gA, gB, md, glse);
    inf_pairs_k<<<N / 8, 256>>>(gA, gB, md, glse, gs);
    finalize_k<<<1, 1>>>(out, gs);
}

// round 4
// speedup vs baseline: 4.2803x; 1.7377x over previous
#include <cuda_runtime.h>
#include <cuda_bf16.h>
#include <cstdint>
#include <math.h>

#define N 4096
#define D 1024
#define NUM_NEG 100

// ---------------- scratch (device globals; no allocation allowed) ----------
__device__ float g_A[N * D];             // projection out A (fp32)
__device__ float g_B[N * D];             // projection out B (fp32)
__device__ __nv_bfloat16 g_zbf[N * D];   // bf16 input staging
__device__ __nv_bfloat16 g_Hbf[N * D];   // bf16 hidden
__device__ __nv_bfloat16 g_Abf[N * D];   // bf16 normalized A / z1
__device__ __nv_bfloat16 g_Bbf[N * D];   // bf16 normalized B / z2
__device__ __nv_bfloat16 g_W1bf[D * D];
__device__ __nv_bfloat16 g_W2bf[D * D];
__device__ float g_rowsum[N];
__device__ float g_colsum[N];
__device__ float g_mrow[N];
__device__ float g_mcol[N];
__device__ float g_lse[N];
__device__ double g_s[4];  // [0]=gcl1 logsum, [1]=gcl2 logsum, [2]=pair_sum, [3]=pair_cnt

// ---------------- small utility kernels ------------------------------------
__global__ void zero_scalars_k(double* s) {
    if (threadIdx.x < 4) s[threadIdx.x] = 0.0;
}

__global__ void zero4_k(float* a, float* b, float* c, float* d) {
    int i = blockIdx.x * blockDim.x + threadIdx.x;
    if (i < N) { a[i] = 0.f; b[i] = 0.f; c[i] = 0.f; d[i] = 0.f; }
}

__global__ void conv_bf16_k(const float* __restrict__ src, __nv_bfloat16* __restrict__ dst, int n) {
    int idx = (blockIdx.x * blockDim.x + threadIdx.x) * 4;
    if (idx < n) {
        float4 v = *(const float4*)&src[idx];
        *(__nv_bfloat162*)&dst[idx] = __floats2bfloat162_rn(v.x, v.y);
        *(__nv_bfloat162*)&dst[idx + 2] = __floats2bfloat162_rn(v.z, v.w);
    }
}

// z1 = (1-g)*zmp1 + g*zsc1 ; z2 = (1-g)*zmp2 + g*zsc2  (bf16 out)
__global__ void combine_bf16_k(const float* __restrict__ zmp1, const float* __restrict__ zsc1,
                               const float* __restrict__ zmp2, const float* __restrict__ zsc2,
                               const float* __restrict__ gamma,
                               __nv_bfloat16* __restrict__ z1, __nv_bfloat16* __restrict__ z2) {
    float g = *gamma;
    int idx = (blockIdx.x * blockDim.x + threadIdx.x) * 4;
    if (idx < N * D) {
        float4 a1 = *(const float4*)&zmp1[idx];
        float4 b1 = *(const float4*)&zsc1[idx];
        float4 a2 = *(const float4*)&zmp2[idx];
        float4 b2 = *(const float4*)&zsc2[idx];
        *(__nv_bfloat162*)&z1[idx]     = __floats2bfloat162_rn((1.f-g)*a1.x + g*b1.x, (1.f-g)*a1.y + g*b1.y);
        *(__nv_bfloat162*)&z1[idx + 2] = __floats2bfloat162_rn((1.f-g)*a1.z + g*b1.z, (1.f-g)*a1.w + g*b1.w);
        *(__nv_bfloat162*)&z2[idx]     = __floats2bfloat162_rn((1.f-g)*a2.x + g*b2.x, (1.f-g)*a2.y + g*b2.y);
        *(__nv_bfloat162*)&z2[idx + 2] = __floats2bfloat162_rn((1.f-g)*a2.z + g*b2.z, (1.f-g)*a2.w + g*b2.w);
    }
}

// normalize rows: read fp32, write bf16 normalized (one warp per row)
__global__ void normalize_k(const float* __restrict__ P, __nv_bfloat16* __restrict__ Pbf) {
    int warp = (blockIdx.x * blockDim.x + threadIdx.x) >> 5;
    int lane = threadIdx.x & 31;
    if (warp >= N) return;
    const float* row = P + (size_t)warp * D;
    __nv_bfloat16* brow = Pbf + (size_t)warp * D;
    float ss = 0.f;
    #pragma unroll 8
    for (int d = lane; d < D; d += 32) { float v = row[d]; ss += v * v; }
    #pragma unroll
    for (int o = 16; o; o >>= 1) ss += __shfl_xor_sync(0xffffffffu, ss, o);
    float inv = 1.0f / sqrtf(ss);
    #pragma unroll 8
    for (int d = lane * 2; d < D; d += 64) {
        *(__nv_bfloat162*)&brow[d] = __floats2bfloat162_rn(row[d] * inv, row[d + 1] * inv);
    }
}

// ---------------- bf16 tensor-core NT GEMM ---------------------------------
// C[i,j] = sum_k A[i,k] * B[j,k]   (A: [M,K] bf16 rm, B: [Nc,K] bf16 rm)
// MODE 0: +bias, ELU, write bf16    MODE 1: +bias, write f32
// MODE 2: sim — exp(acc*1.25) + fused rowsum/colsum + pos-masked mrow/mcol
#define BKT 32

// swizzled smem offset (in bf16 elems): rows of 32 elems (64B), 16B chunks XOR'd
__device__ __forceinline__ int SWZ(int r, int ch) {
    return (r << 5) + ((ch ^ ((r >> 1) & 3)) << 3);
}

__device__ __forceinline__ void mma16816(float* c, const uint32_t* a, const uint32_t* b) {
    asm volatile(
        "mma.sync.aligned.m16n8k16.row.col.f32.bf16.bf16.f32 "
        "{%0,%1,%2,%3}, {%4,%5,%6,%7}, {%8,%9}, {%0,%1,%2,%3};"
        : "+f"(c[0]), "+f"(c[1]), "+f"(c[2]), "+f"(c[3])
        : "r"(a[0]), "r"(a[1]), "r"(a[2]), "r"(a[3]), "r"(b[0]), "r"(b[1]));
}

__device__ __forceinline__ void ldsm4(uint32_t* r, uint32_t saddr) {
    asm volatile("ldmatrix.sync.aligned.m8n8.x4.shared.b16 {%0,%1,%2,%3}, [%4];"
                 : "=r"(r[0]), "=r"(r[1]), "=r"(r[2]), "=r"(r[3]) : "r"(saddr));
}

__device__ __forceinline__ void tile_cp_async(
    const __nv_bfloat16* __restrict__ A, const __nv_bfloat16* __restrict__ B,
    int m0, int n0, int kt, int K,
    uint32_t as, uint32_t bs, int tid) {
    #pragma unroll
    for (int l = 0; l < 2; l++) {
        int idx = tid + l * 256;
        int row = idx >> 2, ch = idx & 3;
        uint32_t da = as + 2 * SWZ(row, ch);
        const __nv_bfloat16* ga = &A[(size_t)(m0 + row) * K + kt + ch * 8];
        asm volatile("cp.async.cg.shared.global [%0], [%1], 16;" :: "r"(da), "l"(ga));
        uint32_t db = bs + 2 * SWZ(row, ch);
        const __nv_bfloat16* gb = &B[(size_t)(n0 + row) * K + kt + ch * 8];
        asm volatile("cp.async.cg.shared.global [%0], [%1], 16;" :: "r"(db), "l"(gb));
    }
}

template <int MODE>
__global__ __launch_bounds__(256, 2)
void mm_bf16_k(const __nv_bfloat16* __restrict__ A, const __nv_bfloat16* __restrict__ B,
               const float* __restrict__ bias, void* __restrict__ Cout,
               const float* __restrict__ pos,
               float* __restrict__ rowsum, float* __restrict__ colsum,
               float* __restrict__ mrow, float* __restrict__ mcol,
               int K, int Nc) {
    __shared__ __align__(16) __nv_bfloat16 As[2][128 * 32];
    __shared__ __align__(16) __nv_bfloat16 Bs[2][128 * 32];
    __shared__ float srow[128], scol[128], srowm[128], scolm[128];

    int tid = threadIdx.x;
    int warp = tid >> 5, lane = tid & 31;
    int g = lane >> 2, t4 = lane & 3;
    int wm = (warp >> 2) * 64;   // 2 warp-rows x 64
    int wn = (warp & 3) * 32;    // 4 warp-cols x 32
    int m0 = blockIdx.y * 128, n0 = blockIdx.x * 128;

    uint32_t asb[2], bsb[2];
    asb[0] = (uint32_t)__cvta_generic_to_shared(As[0]);
    asb[1] = (uint32_t)__cvta_generic_to_shared(As[1]);
    bsb[0] = (uint32_t)__cvta_generic_to_shared(Bs[0]);
    bsb[1] = (uint32_t)__cvta_generic_to_shared(Bs[1]);

    float acc[4][4][4] = {};

    tile_cp_async(A, B, m0, n0, 0, K, asb[0], bsb[0], tid);
    asm volatile("cp.async.commit_group;");

    int lr = lane & 15, lc = lane >> 4;
    int nt = K / BKT;
    for (int kt = 0; kt < nt; kt++) {
        if (kt + 1 < nt) {
            tile_cp_async(A, B, m0, n0, (kt + 1) * BKT, K, asb[(kt + 1) & 1], bsb[(kt + 1) & 1], tid);
            asm volatile("cp.async.commit_group;");
            asm volatile("cp.async.wait_group 1;");
        } else {
            asm volatile("cp.async.wait_group 0;");
        }
        __syncthreads();
        uint32_t ab = asb[kt & 1], bb = bsb[kt & 1];
        #pragma unroll
        for (int ks = 0; ks < 2; ks++) {
            int ch = ks * 2 + lc;
            uint32_t a[4][4], b[2][4];
            #pragma unroll
            for (int mi = 0; mi < 4; mi++)
                ldsm4(a[mi], ab + 2 * SWZ(wm + mi * 16 + lr, ch));
            #pragma unroll
            for (int nb = 0; nb < 2; nb++)
                ldsm4(b[nb], bb + 2 * SWZ(wn + nb * 16 + lr, ch));
            #pragma unroll
            for (int mi = 0; mi < 4; mi++)
                #pragma unroll
                for (int ni = 0; ni < 4; ni++) {
                    uint32_t bf[2] = { b[ni >> 1][ni & 1], b[ni >> 1][(ni & 1) + 2] };
                    mma16816(acc[mi][ni], a[mi], bf);
                }
        }
        __syncthreads();
    }

    if (MODE == 2) {
        if (tid < 128) { srow[tid] = 0.f; scol[tid] = 0.f; srowm[tid] = 0.f; scolm[tid] = 0.f; }
        __syncthreads();
        float rp[4][2] = {}, cp[4][2] = {};
        float rpm[4][2] = {}, cpm[4][2] = {};
        #pragma unroll
        for (int mi = 0; mi < 4; mi++) {
            int r0 = m0 + wm + mi * 16 + g;
            int r1 = r0 + 8;
            #pragma unroll
            for (int ni = 0; ni < 4; ni++) {
                int c = n0 + wn + ni * 8 + t4 * 2;
                float e0 = __expf(acc[mi][ni][0] * 1.25f);   // 1/TAU
                float e1 = __expf(acc[mi][ni][1] * 1.25f);
                float e2 = __expf(acc[mi][ni][2] * 1.25f);
                float e3 = __expf(acc[mi][ni][3] * 1.25f);
                float2 p0 = *(const float2*)&pos[(size_t)r0 * N + c];
                float2 p1 = *(const float2*)&pos[(size_t)r1 * N + c];
                float q00 = pos[(size_t)c * N + r0];
                float q01 = pos[(size_t)(c + 1) * N + r0];
                float q10 = pos[(size_t)c * N + r1];
                float q11 = pos[(size_t)(c + 1) * N + r1];
                rp[mi][0] += e0 + e1;      rp[mi][1] += e2 + e3;
                cp[ni][0] += e0 + e2;      cp[ni][1] += e1 + e3;
                rpm[mi][0] += e0 * p0.x + e1 * p0.y;
                rpm[mi][1] += e2 * p1.x + e3 * p1.y;
                cpm[ni][0] += e0 * q00 + e2 * q10;
                cpm[ni][1] += e1 * q01 + e3 * q11;
            }
        }
        #pragma unroll
        for (int mi = 0; mi < 4; mi++) {
            int r = wm + mi * 16 + g;
            atomicAdd(&srow[r], rp[mi][0]);
            atomicAdd(&srow[r + 8], rp[mi][1]);
            atomicAdd(&srowm[r], rpm[mi][0]);
            atomicAdd(&srowm[r + 8], rpm[mi][1]);
        }
        #pragma unroll
        for (int ni = 0; ni < 4; ni++) {
            int c = wn + ni * 8 + t4 * 2;
            atomicAdd(&scol[c], cp[ni][0]);
            atomicAdd(&scol[c + 1], cp[ni][1]);
            atomicAdd(&scolm[c], cpm[ni][0]);
            atomicAdd(&scolm[c + 1], cpm[ni][1]);
        }
        __syncthreads();
        if (tid < 128) {
            atomicAdd(&rowsum[m0 + tid], srow[tid]);
            atomicAdd(&colsum[n0 + tid], scol[tid]);
            atomicAdd(&mrow[m0 + tid], srowm[tid]);
            atomicAdd(&mcol[n0 + tid], scolm[tid]);
        }
    } else {
        #pragma unroll
        for (int mi = 0; mi < 4; mi++) {
            int r0 = m0 + wm + mi * 16 + g;
            #pragma unroll
            for (int ni = 0; ni < 4; ni++) {
                int c = n0 + wn + ni * 8 + t4 * 2;
                float2 bc = *(const float2*)&bias[c];
                float v0 = acc[mi][ni][0] + bc.x;
                float v1 = acc[mi][ni][1] + bc.y;
                float v2 = acc[mi][ni][2] + bc.x;
                float v3 = acc[mi][ni][3] + bc.y;
                if (MODE == 0) {
                    v0 = (v0 > 0.f) ? v0 : expm1f(v0);
                    v1 = (v1 > 0.f) ? v1 : expm1f(v1);
                    v2 = (v2 > 0.f) ? v2 : expm1f(v2);
                    v3 = (v3 > 0.f) ? v3 : expm1f(v3);
                    __nv_bfloat16* C = (__nv_bfloat16*)Cout;
                    *(__nv_bfloat162*)&C[(size_t)r0 * Nc + c] = __floats2bfloat162_rn(v0, v1);
                    *(__nv_bfloat162*)&C[(size_t)(r0 + 8) * Nc + c] = __floats2bfloat162_rn(v2, v3);
                } else {
                    float* C = (float*)Cout;
                    *(float2*)&C[(size_t)r0 * Nc + c] = make_float2(v0, v1);
                    *(float2*)&C[(size_t)(r0 + 8) * Nc + c] = make_float2(v2, v3);
                }
            }
        }
    }
}

// ---------------- lori reduction --------------------------------------------
__global__ void lori_reduce_k(const float* __restrict__ mrow, const float* __restrict__ rowsum,
                              const float* __restrict__ mcol, const float* __restrict__ colsum,
                              double* __restrict__ target) {
    __shared__ float sm[8];
    int i = blockIdx.x * blockDim.x + threadIdx.x;
    float v = 0.f;
    if (i < N)
        v = logf(mrow[i]) - logf(rowsum[i] + 1e-8f)
          + logf(mcol[i]) - logf(colsum[i] + 1e-8f);
    #pragma unroll
    for (int o = 16; o; o >>= 1) v += __shfl_xor_sync(0xffffffffu, v, o);
    int lane = threadIdx.x & 31, w = threadIdx.x >> 5;
    if (lane == 0) sm[w] = v;
    __syncthreads();
    if (threadIdx.x < 8) {
        float t = sm[threadIdx.x];
        #pragma unroll
        for (int o = 4; o; o >>= 1) t += __shfl_xor_sync(0xffu, t, o);
        if (threadIdx.x == 0) atomicAdd(target, (double)t);
    }
}

// ---------------- InfoNCE: per-row LSE over 100 pseudo-random negatives ----
__global__ __launch_bounds__(128)
void neg_lse_k(const __nv_bfloat16* __restrict__ z1, const __nv_bfloat16* __restrict__ z2,
               const float* __restrict__ md, float* __restrict__ lse) {
    __shared__ float2 zrow[D / 2];
    __shared__ int idxs[NUM_NEG];
    __shared__ float vals[NUM_NEG];
    int i = blockIdx.x;
    const __nv_bfloat162* zi = (const __nv_bfloat162*)(z1 + (size_t)i * D);
    for (int d = threadIdx.x; d < D / 2; d += blockDim.x)
        zrow[d] = __bfloat1622float2(zi[d]);
    if (threadIdx.x == 0) {
        const float* mr = md + (size_t)i * N;
        unsigned start = ((unsigned)i * 2654435761u) & (N - 1);
        int cnt = 0;
        for (unsigned t = 0; cnt < NUM_NEG; t++) {
            int c = (start + t * 97u) & (N - 1);
            if (mr[c] == 0.f) idxs[cnt++] = c;
        }
    }
    __syncthreads();
    int warp = threadIdx.x >> 5, lane = threadIdx.x & 31;
    for (int k = warp; k < NUM_NEG; k += 4) {
        const __nv_bfloat162* zc = (const __nv_bfloat162*)(z2 + (size_t)idxs[k] * D);
        float s = 0.f;
        #pragma unroll 4
        for (int d = lane; d < D / 2; d += 32) {
            float2 x = zrow[d];
            float2 y = __bfloat1622float2(zc[d]);
            s = fmaf(x.x, y.x, s);
            s = fmaf(x.y, y.y, s);
        }
        #pragma unroll
        for (int o = 16; o; o >>= 1) s += __shfl_xor_sync(0xffffffffu, s, o);
        if (lane == 0) vals[k] = s;
    }
    __syncthreads();
    if (threadIdx.x == 0) {
        float m = -1e30f;
        for (int k = 0; k < NUM_NEG; k++) m = fmaxf(m, vals[k]);
        float ss = 0.f;
        for (int k = 0; k < NUM_NEG; k++) ss += __expf((vals[k] - m) * 10.0f);
        lse[i] = m * 10.0f + logf(ss);   // 1/INFONCE_TAU = 10
    }
}

// ---------------- InfoNCE positive pairs (warp per row, z1 row in regs) ----
__global__ void inf_pairs_k(const __nv_bfloat16* __restrict__ z1, const __nv_bfloat16* __restrict__ z2,
                            const float* __restrict__ md, const float* __restrict__ lse,
                            double* __restrict__ s) {
    int warp = (blockIdx.x * blockDim.x + threadIdx.x) >> 5;
    int lane = threadIdx.x & 31;
    if (warp >= N) return;
    int i = warp;
    const float* mr = md + (size_t)i * N;
    const __nv_bfloat162* Zi = (const __nv_bfloat162*)(z1 + (size_t)i * D);
    float2 zi[16];
    #pragma unroll
    for (int u = 0; u < 16; u++) zi[u] = __bfloat1622float2(Zi[lane + u * 32]);
    float L = lse[i];
    float sum = 0.f;
    int cnt = 0;
    for (int jb = 0; jb < N; jb += 32) {
        float pv = mr[jb + lane];
        unsigned mask = __ballot_sync(0xffffffffu, pv > 0.f);
        while (mask) {
            int b = __ffs(mask) - 1;
            mask &= mask - 1;
            int j = jb + b;
            const __nv_bfloat162* Zj = (const __nv_bfloat162*)(z2 + (size_t)j * D);
            float dot = 0.f;
            #pragma unroll
            for (int u = 0; u < 16; u++) {
                float2 y = __bfloat1622float2(Zj[lane + u * 32]);
                dot = fmaf(zi[u].x, y.x, dot);
                dot = fmaf(zi[u].y, y.y, dot);
            }
            #pragma unroll
            for (int o = 16; o; o >>= 1) dot += __shfl_xor_sync(0xffffffffu, dot, o);
            float p = dot * 10.0f;
            float mx = fmaxf(p, L);
            float pp = mx + logf(__expf(p - mx) + __expf(L - mx)) - p;
            sum += pp;
            cnt++;
        }
    }
    if (lane == 0) {
        atomicAdd(&s[2], (double)sum);
        atomicAdd(&s[3], (double)cnt);
    }
}

// ---------------- finalize --------------------------------------------------
__global__ void finalize_k(float* out, const double* s) {
    double gcl = -0.5 * (s[0] + s[1]) / (double)N;   // LAM=0.5 both directions
    out[0] = (float)(gcl + s[2] / s[3]);
}

// ---------------- launcher --------------------------------------------------
extern "C" void kernel_launch(void* const* d_in, const int* in_sizes, int n_in,
                              void* d_out, int out_size) {
    const float* z_mp1 = (const float*)d_in[0];
    const float* z_sc1 = (const float*)d_in[1];
    const float* pos1  = (const float*)d_in[2];
    const float* z_mp2 = (const float*)d_in[3];
    const float* z_sc2 = (const float*)d_in[4];
    const float* pos2  = (const float*)d_in[5];
    const float* md    = (const float*)d_in[6];
    const float* gamma = (const float*)d_in[7];
    const float* W1 = (const float*)d_in[8];
    const float* b1 = (const float*)d_in[9];
    const float* W2 = (const float*)d_in[10];
    const float* b2 = (const float*)d_in[11];
    float* out = (float*)d_out;

    float *gA, *gB, *grow, *gcol, *gmr, *gmc, *glse;
    __nv_bfloat16 *gzbf, *gHbf, *gAbf, *gBbf, *gW1bf, *gW2bf;
    double* gs;
    cudaGetSymbolAddress((void**)&gA, g_A);
    cudaGetSymbolAddress((void**)&gB, g_B);
    cudaGetSymbolAddress((void**)&gzbf, g_zbf);
    cudaGetSymbolAddress((void**)&gHbf, g_Hbf);
    cudaGetSymbolAddress((void**)&gAbf, g_Abf);
    cudaGetSymbolAddress((void**)&gBbf, g_Bbf);
    cudaGetSymbolAddress((void**)&gW1bf, g_W1bf);
    cudaGetSymbolAddress((void**)&gW2bf, g_W2bf);
    cudaGetSymbolAddress((void**)&grow, g_rowsum);
    cudaGetSymbolAddress((void**)&gcol, g_colsum);
    cudaGetSymbolAddress((void**)&gmr, g_mrow);
    cudaGetSymbolAddress((void**)&gmc, g_mcol);
    cudaGetSymbolAddress((void**)&glse, g_lse);
    cudaGetSymbolAddress((void**)&gs, g_s);

    zero_scalars_k<<<1, 32>>>(gs);

    conv_bf16_k<<<(D * D / 4 + 255) / 256, 256>>>(W1, gW1bf, D * D);
    conv_bf16_k<<<(D * D / 4 + 255) / 256, 256>>>(W2, gW2bf, D * D);

    dim3 gproj(D / 128, N / 128);    // (8, 32)
    dim3 gsim(N / 128, N / 128);     // (32, 32)

    const float* zmps[2] = {z_mp1, z_mp2};
    const float* zscs[2] = {z_sc1, z_sc2};
    const float* poss[2] = {pos1, pos2};
    for (int r = 0; r < 2; r++) {
        conv_bf16_k<<<(N * D / 4 + 255) / 256, 256>>>(zmps[r], gzbf, N * D);
        mm_bf16_k<0><<<gproj, 256>>>(gzbf, gW1bf, b1, gHbf, nullptr, nullptr, nullptr, nullptr, nullptr, D, D);
        mm_bf16_k<1><<<gproj, 256>>>(gHbf, gW2bf, b2, gA, nullptr, nullptr, nullptr, nullptr, nullptr, D, D);
        conv_bf16_k<<<(N * D / 4 + 255) / 256, 256>>>(zscs[r], gzbf, N * D);
        mm_bf16_k<0><<<gproj, 256>>>(gzbf, gW1bf, b1, gHbf, nullptr, nullptr, nullptr, nullptr, nullptr, D, D);
        mm_bf16_k<1><<<gproj, 256>>>(gHbf, gW2bf, b2, gB, nullptr, nullptr, nullptr, nullptr, nullptr, D, D);
        normalize_k<<<N / 8, 256>>>(gA, gAbf);
        normalize_k<<<N / 8, 256>>>(gB, gBbf);
        zero4_k<<<N / 256, 256>>>(grow, gcol, gmr, gmc);
        mm_bf16_k<2><<<gsim, 256>>>(gAbf, gBbf, nullptr, nullptr, poss[r], grow, gcol, gmr, gmc, D, N);
        lori_reduce_k<<<N / 256, 256>>>(gmr, grow, gmc, gcol, &gs[r]);
    }

    combine_bf16_k<<<(N * D / 4 + 255) / 256, 256>>>(z_mp1, z_sc1, z_mp2, z_sc2, gamma, gAbf, gBbf);
    neg_lse_k<<<N, 128>>>(gAbf, gBbf, md, glse);
    inf_pairs_k<<<N / 8, 256>>>(gAbf, gBbf, md, glse, gs);
    finalize_k<<<1, 1>>>(out, gs);
}

// round 7
// speedup vs baseline: 5.2202x; 1.2196x over previous
#include <cuda_runtime.h>
#include <cuda_bf16.h>
#include <cstdint>
#include <math.h>

#define N 4096
#define D 1024
#define NUM_NEG 100
#define NT 16            // K=1024 / 64
#define STAGE_BYTES 32768
#define DSMEM 98304      // 3 stages x 32KB (epilogue et overlaps)

// ---------------- scratch (device globals; no allocation allowed) ----------
__device__ __nv_bfloat16 g_Zall[4 * N * D];
__device__ __nv_bfloat16 g_Hall[4 * N * D];
__device__ __nv_bfloat16 g_Pall[4 * N * D];
__device__ __nv_bfloat16 g_W1bf[D * D];
__device__ __nv_bfloat16 g_W2bf[D * D];
__device__ __nv_bfloat16 g_z1[N * D];
__device__ __nv_bfloat16 g_z2[N * D];
__device__ float g_rowsum[N], g_colsum[N], g_mrow[N], g_mcol[N], g_lse[N];
__device__ double g_s[4];  // [0]=gcl1 logsum, [1]=gcl2 logsum, [2]=pair_sum, [3]=pair_cnt

// ---------------- helpers ---------------------------------------------------
__device__ __forceinline__ uint32_t bf2_pack(float a, float b) {
    __nv_bfloat162 t = __floats2bfloat162_rn(a, b);
    return *reinterpret_cast<uint32_t*>(&t);
}

__device__ __forceinline__ void mma16816(float* c, const uint32_t* a, const uint32_t* b) {
    asm volatile(
        "mma.sync.aligned.m16n8k16.row.col.f32.bf16.bf16.f32 "
        "{%0,%1,%2,%3}, {%4,%5,%6,%7}, {%8,%9}, {%0,%1,%2,%3};"
        : "+f"(c[0]), "+f"(c[1]), "+f"(c[2]), "+f"(c[3])
        : "r"(a[0]), "r"(a[1]), "r"(a[2]), "r"(a[3]), "r"(b[0]), "r"(b[1]));
}

__device__ __forceinline__ void ldsm4(uint32_t* r, uint32_t saddr) {
    asm volatile("ldmatrix.sync.aligned.m8n8.x4.shared.b16 {%0,%1,%2,%3}, [%4];"
                 : "=r"(r[0]), "=r"(r[1]), "=r"(r[2]), "=r"(r[3]) : "r"(saddr));
}

template <int W>
__device__ __forceinline__ void cpwait() {
    asm volatile("cp.async.wait_group %0;" :: "n"(W));
}

// swizzled byte offset inside a 128x64 bf16 stage tile (rows of 128B, 16B chunks)
__device__ __forceinline__ uint32_t SWZ64(int r, int ch) {
    return (uint32_t)(r * 128 + ((ch ^ (r & 7)) << 4));
}

// load one 64-K stage of A(128 rows) + B(128 rows), 256 threads
__device__ __forceinline__ void ld_stage(
    const __nv_bfloat16* __restrict__ A, const __nv_bfloat16* __restrict__ B,
    int m0, int n0, int kt, uint32_t st, int tid) {
    #pragma unroll
    for (int i = 0; i < 4; i++) {
        int idx = tid + i * 256;
        int row = idx >> 3, ch = idx & 7;
        const __nv_bfloat16* g = &A[(size_t)(m0 + row) * D + kt + ch * 8];
        asm volatile("cp.async.cg.shared.global [%0], [%1], 16;"
                     :: "r"(st + SWZ64(row, ch)), "l"(g));
    }
    #pragma unroll
    for (int i = 0; i < 4; i++) {
        int idx = tid + i * 256;
        int row = idx >> 3, ch = idx & 7;
        const __nv_bfloat16* g = &B[(size_t)(n0 + row) * D + kt + ch * 8];
        asm volatile("cp.async.cg.shared.global [%0], [%1], 16;"
                     :: "r"(st + 16384 + SWZ64(row, ch)), "l"(g));
    }
}

// ---------------- bf16 HMMA NT GEMM ----------------------------------------
// C[i,j] = sum_k A[i,k]*B[j,k].  MODE 0: +bias+ELU->bf16, 1: +bias->bf16,
// 2: sim epilogue (exp(acc/0.8), rowsum/colsum + pos-masked mrow/mcol)
template <int MODE>
__global__ __launch_bounds__(256, 2)
void mm_bf16_k(const __nv_bfloat16* __restrict__ A, const __nv_bfloat16* __restrict__ B,
               const float* __restrict__ bias, __nv_bfloat16* __restrict__ C,
               const float* __restrict__ pos,
               float* __restrict__ rowsum, float* __restrict__ colsum,
               float* __restrict__ mrow, float* __restrict__ mcol, int Nc) {
    extern __shared__ __align__(16) char dsm[];
    __shared__ float srow[128], srowm[128];

    int tid = threadIdx.x;
    int warp = tid >> 5, lane = tid & 31;
    int g = lane >> 2, t4 = lane & 3;
    int wm = (warp >> 2) * 64;   // 2 warp-rows x 64
    int wn = (warp & 3) * 32;    // 4 warp-cols x 32
    int m0 = blockIdx.y * 128, n0 = blockIdx.x * 128;
    uint32_t sb = (uint32_t)__cvta_generic_to_shared(dsm);

    float acc[4][4][4] = {};

    ld_stage(A, B, m0, n0, 0, sb, tid);
    asm volatile("cp.async.commit_group;");
    ld_stage(A, B, m0, n0, 64, sb + STAGE_BYTES, tid);
    asm volatile("cp.async.commit_group;");

    int lr = lane & 15, lc = lane >> 4;
    for (int s = 0; s < NT; s++) {
        if (s < NT - 1) cpwait<1>(); else cpwait<0>();
        __syncthreads();
        if (s + 2 < NT) {
            ld_stage(A, B, m0, n0, (s + 2) * 64, sb + ((s + 2) % 3) * STAGE_BYTES, tid);
            asm volatile("cp.async.commit_group;");
        }
        uint32_t ab = sb + (s % 3) * STAGE_BYTES;
        uint32_t bb = ab + 16384;
        #pragma unroll
        for (int ks = 0; ks < 4; ks++) {
            int ch = ks * 2 + lc;
            uint32_t a[4][4], b[2][4];
            #pragma unroll
            for (int mi = 0; mi < 4; mi++)
                ldsm4(a[mi], ab + SWZ64(wm + mi * 16 + lr, ch));
            #pragma unroll
            for (int nb = 0; nb < 2; nb++)
                ldsm4(b[nb], bb + SWZ64(wn + nb * 16 + lr, ch));
            #pragma unroll
            for (int mi = 0; mi < 4; mi++)
                #pragma unroll
                for (int ni = 0; ni < 4; ni++) {
                    uint32_t bf[2] = { b[ni >> 1][ni & 1], b[ni >> 1][(ni & 1) + 2] };
                    mma16816(acc[mi][ni], a[mi], bf);
                }
        }
    }
    __syncthreads();   // smem reuse barrier (MODE 2 epilogue overlays stage bufs)

    if (MODE == 2) {
        if (tid < 128) { srow[tid] = 0.f; srowm[tid] = 0.f; }
        __syncthreads();
        float rp[4][2] = {}, rpm[4][2] = {};
        #pragma unroll
        for (int mi = 0; mi < 4; mi++) {
            int r0 = m0 + wm + mi * 16 + g;
            int r1 = r0 + 8;
            #pragma unroll
            for (int ni = 0; ni < 4; ni++) {
                int c = n0 + wn + ni * 8 + t4 * 2;
                float e0 = __expf(acc[mi][ni][0] * 1.25f);   // 1/TAU
                float e1 = __expf(acc[mi][ni][1] * 1.25f);
                float e2 = __expf(acc[mi][ni][2] * 1.25f);
                float e3 = __expf(acc[mi][ni][3] * 1.25f);
                acc[mi][ni][0] = e0; acc[mi][ni][1] = e1;
                acc[mi][ni][2] = e2; acc[mi][ni][3] = e3;
                float2 p0 = *(const float2*)&pos[(size_t)r0 * N + c];
                float2 p1 = *(const float2*)&pos[(size_t)r1 * N + c];
                rp[mi][0] += e0 + e1;            rp[mi][1] += e2 + e3;
                rpm[mi][0] += e0 * p0.x + e1 * p0.y;
                rpm[mi][1] += e2 * p1.x + e3 * p1.y;
            }
        }
        #pragma unroll
        for (int mi = 0; mi < 4; mi++) {
            int r = wm + mi * 16 + g;
            atomicAdd(&srow[r], rp[mi][0]);
            atomicAdd(&srow[r + 8], rp[mi][1]);
            atomicAdd(&srowm[r], rpm[mi][0]);
            atomicAdd(&srowm[r + 8], rpm[mi][1]);
        }
        // transpose e-tile into smem: et[col_local][row_local], pitch 65
        float* et = (float*)dsm + warp * (32 * 65);
        #pragma unroll
        for (int mi = 0; mi < 4; mi++)
            #pragma unroll
            for (int ni = 0; ni < 4; ni++)
                #pragma unroll
                for (int q = 0; q < 4; q++) {
                    int rl = mi * 16 + g + ((q >= 2) ? 8 : 0);
                    int cl = ni * 8 + t4 * 2 + (q & 1);
                    et[cl * 65 + rl] = acc[mi][ni][q];
                }
        __syncwarp();
        // lane owns one column; pos column read is contiguous
        int c = n0 + wn + lane;
        const float4* pc = (const float4*)&pos[(size_t)c * N + m0 + wm];
        float cs = 0.f, csm = 0.f;
        #pragma unroll
        for (int q = 0; q < 16; q++) {
            float4 m4 = pc[q];
            float a0 = et[lane * 65 + q * 4 + 0];
            float a1 = et[lane * 65 + q * 4 + 1];
            float a2 = et[lane * 65 + q * 4 + 2];
            float a3 = et[lane * 65 + q * 4 + 3];
            cs  += a0 + a1 + a2 + a3;
            csm += a0 * m4.x + a1 * m4.y + a2 * m4.z + a3 * m4.w;
        }
        atomicAdd(&colsum[c], cs);
        atomicAdd(&mcol[c], csm);
        __syncthreads();
        if (tid < 128) {
            atomicAdd(&rowsum[m0 + tid], srow[tid]);
            atomicAdd(&mrow[m0 + tid], srowm[tid]);
        }
    } else {
        #pragma unroll
        for (int mi = 0; mi < 4; mi++) {
            int r0 = m0 + wm + mi * 16 + g;
            #pragma unroll
            for (int ni = 0; ni < 4; ni++) {
                int c = n0 + wn + ni * 8 + t4 * 2;
                float2 bc = *(const float2*)&bias[c];
                float v0 = acc[mi][ni][0] + bc.x;
                float v1 = acc[mi][ni][1] + bc.y;
                float v2 = acc[mi][ni][2] + bc.x;
                float v3 = acc[mi][ni][3] + bc.y;
                if (MODE == 0) {
                    v0 = (v0 > 0.f) ? v0 : expm1f(v0);
                    v1 = (v1 > 0.f) ? v1 : expm1f(v1);
                    v2 = (v2 > 0.f) ? v2 : expm1f(v2);
                    v3 = (v3 > 0.f) ? v3 : expm1f(v3);
                }
                *(uint32_t*)&C[(size_t)r0 * Nc + c] = bf2_pack(v0, v1);
                *(uint32_t*)&C[(size_t)(r0 + 8) * Nc + c] = bf2_pack(v2, v3);
            }
        }
    }
}

// ---------------- small utility kernels ------------------------------------
__global__ void zero_scalars_k(double* s) {
    if (threadIdx.x < 4) s[threadIdx.x] = 0.0;
}

__global__ void zero4_k(float* a, float* b, float* c, float* d) {
    int i = blockIdx.x * blockDim.x + threadIdx.x;
    if (i < N) { a[i] = 0.f; b[i] = 0.f; c[i] = 0.f; d[i] = 0.f; }
}

__global__ void conv_bf16_k(const float* __restrict__ src, __nv_bfloat16* __restrict__ dst, int n) {
    int idx = (blockIdx.x * blockDim.x + threadIdx.x) * 4;
    if (idx < n) {
        float4 v = *(const float4*)&src[idx];
        *(__nv_bfloat162*)&dst[idx] = __floats2bfloat162_rn(v.x, v.y);
        *(__nv_bfloat162*)&dst[idx + 2] = __floats2bfloat162_rn(v.z, v.w);
    }
}

__global__ void conv4_k(const float* __restrict__ a, const float* __restrict__ b,
                        const float* __restrict__ c, const float* __restrict__ d,
                        __nv_bfloat16* __restrict__ dst) {
    int idx = (blockIdx.x * blockDim.x + threadIdx.x) * 4;
    if (idx < N * D) {
        const float* srcs[4] = {a, b, c, d};
        #pragma unroll
        for (int t = 0; t < 4; t++) {
            float4 v = *(const float4*)&srcs[t][idx];
            __nv_bfloat16* o = dst + (size_t)t * N * D + idx;
            *(__nv_bfloat162*)&o[0] = __floats2bfloat162_rn(v.x, v.y);
            *(__nv_bfloat162*)&o[2] = __floats2bfloat162_rn(v.z, v.w);
        }
    }
}

// combine -> bf16 z1/z2
__global__ void combine_bf16_k(const float* __restrict__ zmp1, const float* __restrict__ zsc1,
                               const float* __restrict__ zmp2, const float* __restrict__ zsc2,
                               const float* __restrict__ gamma,
                               __nv_bfloat16* __restrict__ z1, __nv_bfloat16* __restrict__ z2) {
    float g = *gamma;
    int idx = (blockIdx.x * blockDim.x + threadIdx.x) * 4;
    if (idx < N * D) {
        float4 a1 = *(const float4*)&zmp1[idx];
        float4 b1 = *(const float4*)&zsc1[idx];
        float4 a2 = *(const float4*)&zmp2[idx];
        float4 b2 = *(const float4*)&zsc2[idx];
        *(__nv_bfloat162*)&z1[idx]     = __floats2bfloat162_rn((1.f-g)*a1.x + g*b1.x, (1.f-g)*a1.y + g*b1.y);
        *(__nv_bfloat162*)&z1[idx + 2] = __floats2bfloat162_rn((1.f-g)*a1.z + g*b1.z, (1.f-g)*a1.w + g*b1.w);
        *(__nv_bfloat162*)&z2[idx]     = __floats2bfloat162_rn((1.f-g)*a2.x + g*b2.x, (1.f-g)*a2.y + g*b2.y);
        *(__nv_bfloat162*)&z2[idx + 2] = __floats2bfloat162_rn((1.f-g)*a2.z + g*b2.z, (1.f-g)*a2.w + g*b2.w);
    }
}

// normalize rows in place (bf16), one warp per row, 4N rows
__global__ void normalize16_k(__nv_bfloat16* __restrict__ P) {
    int row = (blockIdx.x * blockDim.x + threadIdx.x) >> 5;
    int lane = threadIdx.x & 31;
    if (row >= 4 * N) return;
    __nv_bfloat162* p = (__nv_bfloat162*)(P + (size_t)row * D);
    float ss = 0.f;
    float2 v[16];
    #pragma unroll
    for (int u = 0; u < 16; u++) {
        v[u] = __bfloat1622float2(p[lane + u * 32]);
        ss += v[u].x * v[u].x + v[u].y * v[u].y;
    }
    #pragma unroll
    for (int o = 16; o; o >>= 1) ss += __shfl_xor_sync(0xffffffffu, ss, o);
    float inv = rsqrtf(ss);
    #pragma unroll
    for (int u = 0; u < 16; u++)
        p[lane + u * 32] = __floats2bfloat162_rn(v[u].x * inv, v[u].y * inv);
}

// ---------------- lori reduction --------------------------------------------
__global__ void lori_reduce_k(const float* __restrict__ mrow, const float* __restrict__ rowsum,
                              const float* __restrict__ mcol, const float* __restrict__ colsum,
                              double* __restrict__ target) {
    __shared__ float sm[8];
    int i = blockIdx.x * blockDim.x + threadIdx.x;
    float v = 0.f;
    if (i < N)
        v = logf(mrow[i]) - logf(rowsum[i] + 1e-8f)
          + logf(mcol[i]) - logf(colsum[i] + 1e-8f);
    #pragma unroll
    for (int o = 16; o; o >>= 1) v += __shfl_xor_sync(0xffffffffu, v, o);
    int lane = threadIdx.x & 31, w = threadIdx.x >> 5;
    if (lane == 0) sm[w] = v;
    __syncthreads();
    if (threadIdx.x < 8) {
        float t = sm[threadIdx.x];
        #pragma unroll
        for (int o = 4; o; o >>= 1) t += __shfl_xor_sync(0xffu, t, o);
        if (threadIdx.x == 0) atomicAdd(target, (double)t);
    }
}

// ---------------- InfoNCE LSE over 100 pseudo-random negatives -------------
__global__ __launch_bounds__(128)
void neg_lse_k(const __nv_bfloat16* __restrict__ z1, const __nv_bfloat16* __restrict__ z2,
               const float* __restrict__ md, float* __restrict__ lse) {
    __shared__ float2 zrow[D / 2];
    __shared__ int idxs[NUM_NEG];
    __shared__ float vals[NUM_NEG];
    int i = blockIdx.x;
    const __nv_bfloat162* zi = (const __nv_bfloat162*)(z1 + (size_t)i * D);
    for (int d = threadIdx.x; d < D / 2; d += blockDim.x)
        zrow[d] = __bfloat1622float2(zi[d]);
    if (threadIdx.x == 0) {
        const float* mr = md + (size_t)i * N;
        unsigned start = ((unsigned)i * 2654435761u) & (N - 1);
        int cnt = 0;
        for (unsigned t = 0; cnt < NUM_NEG; t++) {
            int c = (start + t * 97u) & (N - 1);
            if (mr[c] == 0.f) idxs[cnt++] = c;
        }
    }
    __syncthreads();
    int warp = threadIdx.x >> 5, lane = threadIdx.x & 31;
    for (int k = warp; k < NUM_NEG; k += 4) {
        const __nv_bfloat162* zc = (const __nv_bfloat162*)(z2 + (size_t)idxs[k] * D);
        float s = 0.f;
        #pragma unroll 4
        for (int d = lane; d < D / 2; d += 32) {
            float2 x = zrow[d];
            float2 y = __bfloat1622float2(zc[d]);
            s = fmaf(x.x, y.x, s);
            s = fmaf(x.y, y.y, s);
        }
        #pragma unroll
        for (int o = 16; o; o >>= 1) s += __shfl_xor_sync(0xffffffffu, s, o);
        if (lane == 0) vals[k] = s;
    }
    __syncthreads();
    if (threadIdx.x == 0) {
        float m = -1e30f;
        for (int k = 0; k < NUM_NEG; k++) m = fmaxf(m, vals[k]);
        float ss = 0.f;
        for (int k = 0; k < NUM_NEG; k++) ss += __expf((vals[k] - m) * 10.0f);
        lse[i] = m * 10.0f + logf(ss);   // 1/INFONCE_TAU = 10
    }
}

// ---------------- InfoNCE positive pairs (warp per row) --------------------
__global__ void inf_pairs_k(const __nv_bfloat16* __restrict__ z1, const __nv_bfloat16* __restrict__ z2,
                            const float* __restrict__ md, const float* __restrict__ lse,
                            double* __restrict__ s) {
    int warp = (blockIdx.x * blockDim.x + threadIdx.x) >> 5;
    int lane = threadIdx.x & 31;
    if (warp >= N) return;
    int i = warp;
    const float* mr = md + (size_t)i * N;
    const __nv_bfloat162* Zi = (const __nv_bfloat162*)(z1 + (size_t)i * D);
    float2 zi[16];
    #pragma unroll
    for (int u = 0; u < 16; u++) zi[u] = __bfloat1622float2(Zi[lane + u * 32]);
    float L = lse[i];
    float sum = 0.f;
    int cnt = 0;
    for (int jb = 0; jb < N; jb += 32) {
        float pv = mr[jb + lane];
        unsigned mask = __ballot_sync(0xffffffffu, pv > 0.f);
        while (mask) {
            int b = __ffs(mask) - 1;
            mask &= mask - 1;
            int j = jb + b;
            const __nv_bfloat162* Zj = (const __nv_bfloat162*)(z2 + (size_t)j * D);
            float dot = 0.f;
            #pragma unroll
            for (int u = 0; u < 16; u++) {
                float2 y = __bfloat1622float2(Zj[lane + u * 32]);
                dot = fmaf(zi[u].x, y.x, dot);
                dot = fmaf(zi[u].y, y.y, dot);
            }
            #pragma unroll
            for (int o = 16; o; o >>= 1) dot += __shfl_xor_sync(0xffffffffu, dot, o);
            float p = dot * 10.0f;
            float mx = fmaxf(p, L);
            float pp = mx + logf(__expf(p - mx) + __expf(L - mx)) - p;
            sum += pp;
            cnt++;
        }
    }
    if (lane == 0) {
        atomicAdd(&s[2], (double)sum);
        atomicAdd(&s[3], (double)cnt);
    }
}

// ---------------- finalize --------------------------------------------------
__global__ void finalize_k(float* out, const double* s) {
    double gcl = -0.5 * (s[0] + s[1]) / (double)N;
    out[0] = (float)(gcl + s[2] / s[3]);
}

// ---------------- launcher --------------------------------------------------
extern "C" void kernel_launch(void* const* d_in, const int* in_sizes, int n_in,
                              void* d_out, int out_size) {
    const float* z_mp1 = (const float*)d_in[0];
    const float* z_sc1 = (const float*)d_in[1];
    const float* pos1  = (const float*)d_in[2];
    const float* z_mp2 = (const float*)d_in[3];
    const float* z_sc2 = (const float*)d_in[4];
    const float* pos2  = (const float*)d_in[5];
    const float* md    = (const float*)d_in[6];
    const float* gamma = (const float*)d_in[7];
    const float* W1 = (const float*)d_in[8];
    const float* b1 = (const float*)d_in[9];
    const float* W2 = (const float*)d_in[10];
    const float* b2 = (const float*)d_in[11];
    float* out = (float*)d_out;

    __nv_bfloat16 *gZ, *gH, *gP, *gW1, *gW2, *gz1, *gz2;
    float *grow, *gcol, *gmr, *gmc, *glse;
    double* gs;
    cudaGetSymbolAddress((void**)&gZ, g_Zall);
    cudaGetSymbolAddress((void**)&gH, g_Hall);
    cudaGetSymbolAddress((void**)&gP, g_Pall);
    cudaGetSymbolAddress((void**)&gW1, g_W1bf);
    cudaGetSymbolAddress((void**)&gW2, g_W2bf);
    cudaGetSymbolAddress((void**)&gz1, g_z1);
    cudaGetSymbolAddress((void**)&gz2, g_z2);
    cudaGetSymbolAddress((void**)&grow, g_rowsum);
    cudaGetSymbolAddress((void**)&gcol, g_colsum);
    cudaGetSymbolAddress((void**)&gmr, g_mrow);
    cudaGetSymbolAddress((void**)&gmc, g_mcol);
    cudaGetSymbolAddress((void**)&glse, g_lse);
    cudaGetSymbolAddress((void**)&gs, g_s);

    cudaFuncSetAttribute(mm_bf16_k<0>, cudaFuncAttributeMaxDynamicSharedMemorySize, DSMEM);
    cudaFuncSetAttribute(mm_bf16_k<1>, cudaFuncAttributeMaxDynamicSharedMemorySize, DSMEM);
    cudaFuncSetAttribute(mm_bf16_k<2>, cudaFuncAttributeMaxDynamicSharedMemorySize, DSMEM);

    zero_scalars_k<<<1, 32>>>(gs);
    conv_bf16_k<<<(D * D / 4 + 255) / 256, 256>>>(W1, gW1, D * D);
    conv_bf16_k<<<(D * D / 4 + 255) / 256, 256>>>(W2, gW2, D * D);
    conv4_k<<<(N * D / 4 + 255) / 256, 256>>>(z_mp1, z_sc1, z_mp2, z_sc2, gZ);

    // batched projection MLP: layer1 (ELU) then layer2, M = 16384
    dim3 gproj(D / 128, 4 * N / 128);      // (8, 128)
    mm_bf16_k<0><<<gproj, 256, DSMEM>>>(gZ, gW1, b1, gH, nullptr, nullptr, nullptr, nullptr, nullptr, D);
    mm_bf16_k<1><<<gproj, 256, DSMEM>>>(gH, gW2, b2, gP, nullptr, nullptr, nullptr, nullptr, nullptr, D);
    normalize16_k<<<4 * N / 8, 256>>>(gP);

    dim3 gsim(N / 128, N / 128);           // (32, 32)
    const float* poss[2] = {pos1, pos2};
    for (int r = 0; r < 2; r++) {
        zero4_k<<<N / 256, 256>>>(grow, gcol, gmr, gmc);
        mm_bf16_k<2><<<gsim, 256, DSMEM>>>(gP + (size_t)(2 * r) * N * D,
                                           gP + (size_t)(2 * r + 1) * N * D,
                                           nullptr, nullptr, poss[r],
                                           grow, gcol, gmr, gmc, N);
        lori_reduce_k<<<N / 256, 256>>>(gmr, grow, gmc, gcol, &gs[r]);
    }

    combine_bf16_k<<<(N * D / 4 + 255) / 256, 256>>>(z_mp1, z_sc1, z_mp2, z_sc2, gamma, gz1, gz2);
    neg_lse_k<<<N, 128>>>(gz1, gz2, md, glse);
    inf_pairs_k<<<N / 8, 256>>>(gz1, gz2, md, glse, gs);
    finalize_k<<<1, 1>>>(out, gs);
}